// round 13
// baseline (speedup 1.0000x reference)
#include <cuda_runtime.h>
#include <cstdint>

#define NB 32
#define KB 32
#define TB 128
#define HB 768
#define H2 1536

// Output layout (float32, concat of flattened outputs)
#define OFF_SCORE   0
#define OFF_ENC     1024
#define OFF_MASK    3146752
#define OFF_USE     3150848
#define OFF_IDX     3175424

#define USPLIT 8
#define GCH    (HB / USPLIT)   // 96

// Scratch (device globals — allocation is forbidden)
__device__ float    g_cqk_pro[NB * HB];
__device__ float    g_upart[USPLIT][NB][HB];
__device__ unsigned g_cntU, g_done;

__device__ __forceinline__ unsigned ld_acq(const unsigned* p) {
    unsigned v;
    asm volatile("ld.global.acquire.gpu.u32 %0, [%1];" : "=r"(v) : "l"(p));
    return v;
}

// ---------------------------------------------------------------------------
// Launch 1 (1184 blocks x 256): gather-first streaming + A-GEMM.
//   [0,384):     big gather, 8 float4/thread, __ldcs/__stcs streaming so the
//                24 MB of copy traffic never occupies L2 (no reuse).
//   [384,416):   small gathers
//   [416,1184):  A-GEMM  cqk_pro[n,h] = cqk[n,:] . W_cqk[h,:] + b[h]
// Wave 1 at 4 blocks/SM (64 regs) = ~592 blocks: entire gather + 176 A.
// ---------------------------------------------------------------------------
#define B1_SM0  384
#define B1_A0   416
#define GRID1   1184

__global__ void __launch_bounds__(256) k1_gather_agemm(
    const float* __restrict__ ctx1,
    const float* __restrict__ tku,
    const float* __restrict__ Wcqk,
    const float* __restrict__ bcqk,
    const float* __restrict__ pe0,
    const float* __restrict__ pe1,
    const int*   __restrict__ pm,
    const int*   __restrict__ pt,
    const int*   __restrict__ label,
    float* __restrict__ cqkp,
    float* __restrict__ out)
{
    const int b   = blockIdx.x;
    const int tid = threadIdx.x;

    if (b < B1_SM0) {
        // ---- big gather: 384 blocks x 2048 float4, streaming both ways
        const int n     = b / 12;             // 12 blocks per n
        const int chunk = b % 12;
        const float4* src = (const float4*)(pe0 + ((size_t)n * KB + label[n]) * (size_t)TB * HB);
        float4* dst = (float4*)(out + OFF_ENC + (size_t)n * TB * HB);
        const int i0 = chunk * 2048 + tid;
        float4 v[8];
#pragma unroll
        for (int j = 0; j < 8; j++) v[j] = __ldcs(&src[i0 + j * 256]);
#pragma unroll
        for (int j = 0; j < 8; j++) __stcs(&dst[i0 + j * 256], v[j]);

    } else if (b < B1_A0) {
        // ---- small gathers
        const int n    = b - B1_SM0;
        const int lab  = label[n];
        const int base = (n * KB + lab) * TB;
        for (int t = tid; t < TB; t += 256) {
            out[OFF_MASK + n * TB + t] = (pm[base + t] != 0) ? 1.f : 0.f;
            out[OFF_IDX  + n * TB + t] = (float)pt[base + t];
        }
        const size_t ub = ((size_t)n * KB + lab) * HB;
        for (int h = tid; h < HB; h += 256)
            out[OFF_USE + n * HB + h] = pe1[ub + h];

    } else {
        // ---- A-GEMM: warp -> (4 h, 1 n); block shares the same 4 W rows
        const int wid  = tid >> 5;
        const int lane = tid & 31;
        const int gw   = (b - B1_A0) * 8 + wid;
        const int hg   = gw >> 5;
        const int n    = gw & 31;
        const int h0   = hg * 4;

        float4 a[12];
        const float4* arow0 = (const float4*)(ctx1 + (size_t)n * 3 * HB + 2 * HB);
        const float4* arow1 = (const float4*)(tku  + (size_t)n * HB);
#pragma unroll
        for (int i = 0; i < 6; i++) a[i]     = arow0[i * 32 + lane];
#pragma unroll
        for (int i = 0; i < 6; i++) a[i + 6] = arow1[i * 32 + lane];

        float acc[4];
#pragma unroll
        for (int hh = 0; hh < 4; hh++) {
            const float4* w = (const float4*)(Wcqk + (size_t)(h0 + hh) * H2);
            float s = 0.f;
#pragma unroll
            for (int i = 0; i < 12; i++) {
                float4 wv = w[i * 32 + lane];
                s += a[i].x * wv.x + a[i].y * wv.y + a[i].z * wv.z + a[i].w * wv.w;
            }
            acc[hh] = s;
        }
#pragma unroll
        for (int hh = 0; hh < 4; hh++) {
#pragma unroll
            for (int o = 16; o; o >>= 1)
                acc[hh] += __shfl_xor_sync(0xFFFFFFFFu, acc[hh], o);
        }
        if (lane == 0) {
            float* dst = cqkp + (size_t)n * HB + h0;
            dst[0] = acc[0] + bcqk[h0 + 0];
            dst[1] = acc[1] + bcqk[h0 + 1];
            dst[2] = acc[2] + bcqk[h0 + 2];
            dst[3] = acc[3] + bcqk[h0 + 3];
        }
    }
}

// ---------------------------------------------------------------------------
// Launch 2 (320 blocks x 256): dependency chain.
//   [0,192):   u partials (split-K, float4-dense warps; no spin).
//   [192,320): score — compute c[n]=bk.cqkp[n] and prefetch pe1 (streaming)
//              BEFORE the spin, spin on 192 u producers, sum partials, dot.
// ---------------------------------------------------------------------------
#define B2_U    192
#define B2_S0   192
#define GRID2   320
#define N_PROD  192

__global__ void __launch_bounds__(256) k2_chain(
    const float* __restrict__ cqkp,
    const float* __restrict__ Wk,
    const float* __restrict__ bk,
    const float* __restrict__ pe1,
    const int*   __restrict__ ckm,
    float* __restrict__ out)
{
    const int b    = blockIdx.x;
    const int tid  = threadIdx.x;
    const int wid  = tid >> 5;
    const int lane = tid & 31;

    if (b < B2_U) {
        // ---- u partial: b = htile*32 + split*4 + ngroup  (htile 0..5)
        const int htile = b >> 5;
        const int rem   = b & 31;
        const int split = rem >> 2;
        const int ng    = rem & 3;
        const int n     = ng * 8 + wid;
        const int h0    = htile * 128 + lane * 4;
        const int g0    = split * GCH;

        const float4* wrow = (const float4*)(Wk + (size_t)g0 * HB + h0);
        const float*  cr   = cqkp + (size_t)n * HB + g0;

        float4 acc0 = {0.f, 0.f, 0.f, 0.f};
        float4 acc1 = {0.f, 0.f, 0.f, 0.f};
#pragma unroll
        for (int gb = 0; gb < GCH; gb += 32) {
            float cg = cr[gb + lane];
            const float4* wb = wrow + (size_t)gb * (HB / 4);
#pragma unroll
            for (int j = 0; j < 32; j += 2) {
                float c0 = __shfl_sync(0xFFFFFFFFu, cg, j);
                float c1 = __shfl_sync(0xFFFFFFFFu, cg, j + 1);
                float4 w0 = wb[(size_t)j * (HB / 4)];
                float4 w1 = wb[(size_t)(j + 1) * (HB / 4)];
                acc0.x += c0 * w0.x; acc0.y += c0 * w0.y;
                acc0.z += c0 * w0.z; acc0.w += c0 * w0.w;
                acc1.x += c1 * w1.x; acc1.y += c1 * w1.y;
                acc1.z += c1 * w1.z; acc1.w += c1 * w1.w;
            }
        }
        float4 r;
        r.x = acc0.x + acc1.x; r.y = acc0.y + acc1.y;
        r.z = acc0.z + acc1.z; r.w = acc0.w + acc1.w;
        *(float4*)(&g_upart[split][n][h0]) = r;

        __threadfence();
        __syncthreads();
        if (tid == 0) atomicAdd(&g_cntU, 1u);

    } else {
        // ---- score block: (n, 8 k's)
        const int bb = b - B2_S0;
        const int n  = bb >> 2;
        const int kg = bb & 3;
        const int k  = kg * 8 + wid;

        // prefetch pe1 row (read-once -> streaming)
        const float4* p = (const float4*)(pe1 + ((size_t)n * KB + k) * HB);
        float4 a[6];
#pragma unroll
        for (int i = 0; i < 6; i++) a[i] = __ldcs(&p[i * 32 + lane]);

        // c[n] = bk . cqkp[n]  (ready at launch start; L2-hot)
        const float4* cc  = (const float4*)(cqkp + (size_t)n * HB);
        const float4* bb4 = (const float4*)bk;
        float cpart = 0.f;
#pragma unroll
        for (int i = 0; i < 6; i++) {
            float4 x = cc[i * 32 + lane];
            float4 y = bb4[i * 32 + lane];
            cpart += x.x * y.x + x.y * y.y + x.z * y.z + x.w * y.w;
        }
#pragma unroll
        for (int o = 16; o; o >>= 1) cpart += __shfl_xor_sync(0xFFFFFFFFu, cpart, o);

        const int mask_v = ckm[n * KB + k];

        if (tid == 0) {
            while (ld_acq(&g_cntU) < (unsigned)N_PROD) __nanosleep(32);
        }
        __syncthreads();

        float s = 0.f;
#pragma unroll
        for (int i = 0; i < 6; i++) {
            const int hh = (i * 32 + lane) * 4;
            float4 q0 = *(const float4*)(&g_upart[0][n][hh]);
#pragma unroll
            for (int sp = 1; sp < USPLIT; sp++) {
                float4 qs = *(const float4*)(&g_upart[sp][n][hh]);
                q0.x += qs.x; q0.y += qs.y; q0.z += qs.z; q0.w += qs.w;
            }
            s += a[i].x * q0.x + a[i].y * q0.y + a[i].z * q0.z + a[i].w * q0.w;
        }
#pragma unroll
        for (int o = 16; o; o >>= 1) s += __shfl_xor_sync(0xFFFFFFFFu, s, o);
        if (lane == 0)
            out[OFF_SCORE + n * KB + k] = (mask_v != 0) ? (s + cpart) : -1e20f;
    }

    // ---- replay-safe reset: last block out clears the counters
    __syncthreads();
    if (tid == 0) {
        unsigned v = atomicAdd(&g_done, 1u);
        if (v == (unsigned)(GRID2 - 1)) {
            g_cntU = 0u;
            g_done = 0u;
            __threadfence();
        }
    }
}

extern "C" void kernel_launch(void* const* d_in, const int* in_sizes, int n_in,
                              void* d_out, int out_size)
{
    const float* ctx1 = (const float*)d_in[0];
    const float* tku  = (const float*)d_in[1];
    const float* pe0  = (const float*)d_in[2];
    const float* pe1  = (const float*)d_in[3];
    const int*   pm   = (const int*)d_in[4];
    const int*   ckm  = (const int*)d_in[5];
    const int*   lab  = (const int*)d_in[6];
    const int*   pt   = (const int*)d_in[7];
    const float* Wcqk = (const float*)d_in[8];
    const float* bcqk = (const float*)d_in[9];
    const float* Wk   = (const float*)d_in[10];
    const float* bk   = (const float*)d_in[11];

    float* out = (float*)d_out;

    float* d_cqkp; cudaGetSymbolAddress((void**)&d_cqkp, g_cqk_pro);

    k1_gather_agemm<<<GRID1, 256>>>(ctx1, tku, Wcqk, bcqk, pe0, pe1,
                                    pm, pt, lab, d_cqkp, out);
    k2_chain<<<GRID2, 256>>>(d_cqkp, Wk, bk, pe1, ckm, out);
}